// round 8
// baseline (speedup 1.0000x reference)
#include <cuda_runtime.h>
#include <cstdint>

// Problem constants (fixed by the dataset)
constexpr int Bc = 8;
constexpr int Nc = 100000;
constexpr int Ec = 3200000;

// Persistent grid: 888 = 148 SMs x 6 blocks; __launch_bounds__(256,6) caps
// regs at 42 -> 256*6*42 = 64512 <= 64K RF, 1536 thr/SM <= 2048. All blocks
// resident in wave 1 (GB300 has 152 SMs) -> grid barrier is deadlock-free.
constexpr int GRID = 888;
constexpr int TPB  = 256;
constexpr int TOT  = GRID * TPB;

// Scratch (device globals — no allocation allowed in kernel_launch)
__device__ __align__(16) float g_heads_t[Nc * Bc];   // heads transposed to (N, 8)
__device__ __align__(16) float g_net[Nc * Bc];       // net_flows, node-major (N, 8)
__device__ float g_partials[GRID];                   // continuity partial sums
__device__ volatile unsigned g_bar_gen;              // barrier generation
__device__ unsigned g_bar_count;                     // barrier arrival count

__device__ __forceinline__ void red_add_v4(float* p, float4 v) {
    asm volatile("red.global.add.v4.f32 [%0], {%1, %2, %3, %4};"
                 :: "l"(__cvta_generic_to_global(p)),
                    "f"(v.x), "f"(v.y), "f"(v.z), "f"(v.w)
                 : "memory");
}

// Deterministic grid-wide barrier (generation counter; monotone across graph
// replays, so no per-launch reset is needed).
__device__ __forceinline__ void grid_barrier() {
    __syncthreads();
    if (threadIdx.x == 0) {
        unsigned gen = g_bar_gen;
        __threadfence();
        if (atomicAdd(&g_bar_count, 1u) == GRID - 1) {
            g_bar_count = 0;
            __threadfence();
            g_bar_gen = gen + 1;
        } else {
            while (g_bar_gen == gen) { __nanosleep(32); }
        }
        __threadfence();
    }
    __syncthreads();
}

// Deterministic block reduction helper (valid result on thread 0)
__device__ __forceinline__ float block_reduce(float v) {
    __shared__ float sh[32];
    int lane = threadIdx.x & 31;
    int wid  = threadIdx.x >> 5;
    #pragma unroll
    for (int o = 16; o; o >>= 1) v += __shfl_down_sync(0xffffffffu, v, o);
    if (lane == 0) sh[wid] = v;
    __syncthreads();
    int nw = blockDim.x >> 5;
    v = (threadIdx.x < nw) ? sh[threadIdx.x] : 0.f;
    if (wid == 0) {
        #pragma unroll
        for (int o = 16; o; o >>= 1) v += __shfl_down_sync(0xffffffffu, v, o);
    }
    return v;
}

// ---------------------------------------------------------------------------
// Fused persistent kernel: prep -> edge -> loss -> final, separated by grid
// barriers. Edge phase = R7's measured-best lane-pair form (2 threads/edge).
// edge_index / reservoir_nodes are INT32 (JAX x64-disabled randint).
// ---------------------------------------------------------------------------
__global__ void __launch_bounds__(TPB, 6)
fused_kernel(const float* __restrict__ heads,
             const float* __restrict__ demands,
             const int*   __restrict__ ei,
             const float2* __restrict__ ea,
             const int*   __restrict__ res,
             const float* __restrict__ rhead,
             float* __restrict__ out) {
    const int tid0 = blockIdx.x * TPB + threadIdx.x;

    // ---- Phase 0: transpose heads (B,N)->(N,8), zero net accumulator ----
    {
        int t = tid0;                       // 2*Nc = 200k < TOT: single pass
        int n = t >> 1;
        int h = t & 1;
        if (n < Nc) {
            const float* hp = heads + (h * 4) * Nc + n;
            float4 a;
            a.x = hp[0 * Nc];
            a.y = hp[1 * Nc];
            a.z = hp[2 * Nc];
            a.w = hp[3 * Nc];
            reinterpret_cast<float4*>(g_heads_t)[2 * n + h] = a;
            reinterpret_cast<float4*>(g_net)[2 * n + h] =
                make_float4(0.f, 0.f, 0.f, 0.f);
        }
    }
    grid_barrier();

    // ---- Phase 1: edges (lane-pair: even lane batches 0-3, odd 4-7) ----
    {
        const float4* ht = reinterpret_cast<const float4*>(g_heads_t);
        for (int t = tid0; t < 2 * Ec; t += TOT) {   // TOT even -> h fixed/thread
            int e = t >> 1;
            int h = t & 1;

            int s = ei[e];
            int d = ei[Ec + e];
            float cond = ea[e].x;

            float4 hs = ht[2 * s + h];
            float4 hd = ht[2 * d + h];

            float4 f;
            f.x = cond * (hs.x - hd.x);
            f.y = cond * (hs.y - hd.y);
            f.z = cond * (hs.z - hd.z);
            f.w = cond * (hs.w - hd.w);

            // flows = out + 3 is only 4B-aligned — scalar stores mandatory
            float* flows = out + 3;
            long long b0 = (long long)(4 * h) * Ec + e;
            flows[b0]          = f.x;
            flows[b0 + 1LL*Ec] = f.y;
            flows[b0 + 2LL*Ec] = f.z;
            flows[b0 + 3LL*Ec] = f.w;

            if (s != d) {   // self-edge contributes exactly zero net flow
                red_add_v4(&g_net[s * 8 + 4 * h], f);
                float4 nf = make_float4(-f.x, -f.y, -f.z, -f.w);
                red_add_v4(&g_net[d * 8 + 4 * h], nf);
            }
        }
    }
    grid_barrier();

    // ---- Phase 2: continuity partials (one node per thread, single pass) ----
    {
        float acc = 0.f;
        int n = tid0;
        if (n < Nc) {
            const float4* nf = reinterpret_cast<const float4*>(g_net);
            float4 a = nf[2 * n];
            float4 b = nf[2 * n + 1];
            float v;
            v = a.x - demands[0 * Nc + n]; acc += v * v;
            v = a.y - demands[1 * Nc + n]; acc += v * v;
            v = a.z - demands[2 * Nc + n]; acc += v * v;
            v = a.w - demands[3 * Nc + n]; acc += v * v;
            v = b.x - demands[4 * Nc + n]; acc += v * v;
            v = b.y - demands[5 * Nc + n]; acc += v * v;
            v = b.z - demands[6 * Nc + n]; acc += v * v;
            v = b.w - demands[7 * Nc + n]; acc += v * v;
        }
        float s = block_reduce(acc);
        if (threadIdx.x == 0) g_partials[blockIdx.x] = s;
    }
    grid_barrier();

    // ---- Phase 3: block 0 sums partials + boundary loss, writes scalars ----
    if (blockIdx.x == 0) {
        int tid = threadIdx.x;
        float acc = 0.f;
        for (int i = tid; i < GRID; i += TPB) acc += g_partials[i];
        float csum = block_reduce(acc);
        __syncthreads();

        float rh = rhead[0];
        float acc2 = 0.f;
        for (int i = tid; i < Bc * 64; i += TPB) {
            int b = i >> 6;
            int j = i & 63;
            int r = res[j];
            float v = heads[(long long)b * Nc + r] - rh;
            acc2 += v * v;
        }
        float bsum = block_reduce(acc2);

        if (tid == 0) {
            float c  = csum / (float)(Bc * Nc);
            float bl = bsum / (float)(Bc * 64);
            out[0] = c;
            out[1] = bl;
            out[2] = c + bl;   // LAMBDA_PHYSICS = 1.0
        }
    }
}

// ---------------------------------------------------------------------------
// Launch: one persistent fused kernel. Graph-capturable.
// ---------------------------------------------------------------------------
extern "C" void kernel_launch(void* const* d_in, const int* in_sizes, int n_in,
                              void* d_out, int out_size) {
    const float*  node_heads = (const float*)d_in[0];
    const float*  demands    = (const float*)d_in[1];
    const int*    edge_index = (const int*)d_in[2];     // int32!
    const float2* edge_attr  = (const float2*)d_in[3];
    const int*    res_nodes  = (const int*)d_in[4];     // int32!
    const float*  res_head   = (const float*)d_in[5];

    float* out = (float*)d_out;   // [c, b, total, flows(8*E)]

    fused_kernel<<<GRID, TPB>>>(node_heads, demands, edge_index, edge_attr,
                                res_nodes, res_head, out);
}

// round 9
// speedup vs baseline: 1.0660x; 1.0660x over previous
#include <cuda_runtime.h>
#include <cstdint>

// Problem constants (fixed by the dataset)
constexpr int Bc = 8;
constexpr int Nc = 100000;
constexpr int Ec = 3200000;
constexpr int LOSS_BLOCKS = 196;   // 196*256*2 >= 2*Nc: exactly 2 nodes/thread

// Scratch (device globals — no allocation allowed in kernel_launch)
__device__ __align__(16) float g_heads_t[Nc * Bc];   // heads transposed to (N, 8)
__device__ __align__(16) float g_net[Nc * Bc];       // net_flows, node-major (N, 8)
__device__ float g_partials[LOSS_BLOCKS];            // continuity partial sums
__device__ float g_boundary;                         // boundary-loss sum (from prep)

__device__ __forceinline__ void red_add_v4(float* p, float4 v) {
    asm volatile("red.global.add.v4.f32 [%0], {%1, %2, %3, %4};"
                 :: "l"(__cvta_generic_to_global(p)),
                    "f"(v.x), "f"(v.y), "f"(v.z), "f"(v.w)
                 : "memory");
}

// Deterministic block reduction helper (valid result on thread 0)
__device__ __forceinline__ float block_reduce(float v) {
    __shared__ float sh[32];
    int lane = threadIdx.x & 31;
    int wid  = threadIdx.x >> 5;
    #pragma unroll
    for (int o = 16; o; o >>= 1) v += __shfl_down_sync(0xffffffffu, v, o);
    if (lane == 0) sh[wid] = v;
    __syncthreads();
    int nw = blockDim.x >> 5;
    v = (threadIdx.x < nw) ? sh[threadIdx.x] : 0.f;
    if (wid == 0) {
        #pragma unroll
        for (int o = 16; o; o >>= 1) v += __shfl_down_sync(0xffffffffu, v, o);
    }
    return v;
}

// ---------------------------------------------------------------------------
// Kernel 1: transpose heads (B,N)->(N,8), zero the net accumulator.
// One thread per (node, batch-half); 512-thread blocks.
// Block 0 ALSO computes the boundary loss sum (depends only on heads/res/
// rhead) — hidden under the other 390 blocks' transpose work.
// ---------------------------------------------------------------------------
__global__ void __launch_bounds__(512)
prep_kernel(const float* __restrict__ heads,
            const int*   __restrict__ res,
            const float* __restrict__ rhead) {
    int t = blockIdx.x * blockDim.x + threadIdx.x;
    int n = t >> 1;
    int h = t & 1;          // which half: batches 0-3 or 4-7
    if (n < Nc) {
        const float* hp = heads + (h * 4) * Nc + n;
        float4 a;
        a.x = hp[0 * Nc];
        a.y = hp[1 * Nc];
        a.z = hp[2 * Nc];
        a.w = hp[3 * Nc];
        reinterpret_cast<float4*>(g_heads_t)[2 * n + h] = a;
        reinterpret_cast<float4*>(g_net)[2 * n + h] = make_float4(0.f, 0.f, 0.f, 0.f);
    }

    if (blockIdx.x == 0) {  // boundary loss: 512 threads, one (b, j) each
        float rh = rhead[0];
        int b = threadIdx.x >> 6;   // 8 batches
        int j = threadIdx.x & 63;   // 64 reservoir nodes
        int r = res[j];
        float v = heads[(long long)b * Nc + r] - rh;
        float bsum = block_reduce(v * v);
        if (threadIdx.x == 0) g_boundary = bsum;
    }
}

// ---------------------------------------------------------------------------
// Kernel 2: lane-pair decomposition — 2 threads per edge (even lane: batches
// 0-3, odd lane: batches 4-7). Adjacent lanes touch the SAME 128-B L1 line
// per gathered endpoint -> gather L1 wavefronts halve vs one-thread-per-edge.
// ei/ea loads are pair-broadcast (merged); LTS sector traffic unchanged.
// edge_index is INT32 (JAX x64-disabled: "int64" randint is silently int32).
// ---------------------------------------------------------------------------
__global__ void __launch_bounds__(256)
edge_kernel(const int* __restrict__ ei,
            const float2* __restrict__ ea,
            float* __restrict__ flows) {
    int t = blockIdx.x * blockDim.x + threadIdx.x;   // grid exact: 2*Ec % 256 == 0
    int e = t >> 1;
    int h = t & 1;          // batch half

    int s = ei[e];
    int d = ei[Ec + e];
    float cond = ea[e].x;

    const float4* ht = reinterpret_cast<const float4*>(g_heads_t);
    float4 hs = ht[2 * s + h];
    float4 hd = ht[2 * d + h];

    float4 f;
    f.x = cond * (hs.x - hd.x);
    f.y = cond * (hs.y - hd.y);
    f.z = cond * (hs.z - hd.z);
    f.w = cond * (hs.w - hd.w);

    // flows output (B, E): per batch row, same-parity lanes write consecutive e.
    // NOTE: flows = d_out + 3 is only 4B-aligned — scalar stores are mandatory.
    long long b0 = (long long)(4 * h) * Ec + e;
    flows[b0]           = f.x;
    flows[b0 + 1LL*Ec]  = f.y;
    flows[b0 + 2LL*Ec]  = f.z;
    flows[b0 + 3LL*Ec]  = f.w;

    if (s != d) {  // self-edge contributes exactly zero net flow
        red_add_v4(&g_net[s * 8 + 4 * h], f);
        float4 nf = make_float4(-f.x, -f.y, -f.z, -f.w);
        red_add_v4(&g_net[d * 8 + 4 * h], nf);
    }
}

// ---------------------------------------------------------------------------
// Kernel 3: continuity partial sums. Balanced grid: 2 nodes per thread.
// ---------------------------------------------------------------------------
__global__ void __launch_bounds__(256)
loss_kernel(const float* __restrict__ demands) {
    float acc = 0.f;
    const float4* nf = reinterpret_cast<const float4*>(g_net);
    for (int n = blockIdx.x * blockDim.x + threadIdx.x; n < Nc;
         n += gridDim.x * blockDim.x) {
        float4 a = nf[2 * n];
        float4 b = nf[2 * n + 1];
        float v;
        v = a.x - demands[0 * Nc + n]; acc += v * v;
        v = a.y - demands[1 * Nc + n]; acc += v * v;
        v = a.z - demands[2 * Nc + n]; acc += v * v;
        v = a.w - demands[3 * Nc + n]; acc += v * v;
        v = b.x - demands[4 * Nc + n]; acc += v * v;
        v = b.y - demands[5 * Nc + n]; acc += v * v;
        v = b.z - demands[6 * Nc + n]; acc += v * v;
        v = b.w - demands[7 * Nc + n]; acc += v * v;
    }
    float s = block_reduce(acc);
    if (threadIdx.x == 0) g_partials[blockIdx.x] = s;
}

// ---------------------------------------------------------------------------
// Kernel 4: final — sum the 196 partials + precomputed boundary sum,
// write the 3 scalars. Single small block.
// ---------------------------------------------------------------------------
__global__ void __launch_bounds__(256)
final_kernel(float* __restrict__ out) {
    int tid = threadIdx.x;
    float acc = (tid < LOSS_BLOCKS) ? g_partials[tid] : 0.f;
    float csum = block_reduce(acc);
    if (tid == 0) {
        float c  = csum / (float)(Bc * Nc);
        float bl = g_boundary / (float)(Bc * 64);
        out[0] = c;
        out[1] = bl;
        out[2] = c + bl;  // LAMBDA_PHYSICS = 1.0
    }
}

// ---------------------------------------------------------------------------
// Launch: prep(+boundary) -> edge -> loss -> final. Graph-capturable.
// ---------------------------------------------------------------------------
extern "C" void kernel_launch(void* const* d_in, const int* in_sizes, int n_in,
                              void* d_out, int out_size) {
    const float*  node_heads = (const float*)d_in[0];
    const float*  demands    = (const float*)d_in[1];
    const int*    edge_index = (const int*)d_in[2];     // int32!
    const float2* edge_attr  = (const float2*)d_in[3];
    const int*    res_nodes  = (const int*)d_in[4];     // int32!
    const float*  res_head   = (const float*)d_in[5];

    float* out   = (float*)d_out;
    float* flows = out + 3;  // output layout: [c, b, total, flows(8*E)]

    prep_kernel<<<(2 * Nc + 511) / 512, 512>>>(node_heads, res_nodes, res_head);
    edge_kernel<<<(2 * Ec) / 256, 256>>>(edge_index, edge_attr, flows);
    loss_kernel<<<LOSS_BLOCKS, 256>>>(demands);
    final_kernel<<<1, 256>>>(out);
}

// round 10
// speedup vs baseline: 1.1165x; 1.0474x over previous
#include <cuda_runtime.h>
#include <cstdint>

// Problem constants (fixed by the dataset)
constexpr int Bc = 8;
constexpr int Nc = 100000;
constexpr int Ec = 3200000;
constexpr int LOSS_BLOCKS = 196;   // 196*256*2 >= 2*Nc: exactly 2 nodes/thread

// Scratch (device globals — no allocation allowed in kernel_launch)
__device__ __align__(16) float g_heads_t[Nc * Bc];   // heads transposed to (N, 8)
__device__ __align__(16) float g_net[Nc * Bc];       // net_flows, node-major (N, 8)
__device__ float g_partials[LOSS_BLOCKS];            // continuity partial sums
__device__ float g_boundary;                         // boundary-loss sum

__device__ __forceinline__ void red_add_v4(float* p, float4 v) {
    asm volatile("red.global.add.v4.f32 [%0], {%1, %2, %3, %4};"
                 :: "l"(__cvta_generic_to_global(p)),
                    "f"(v.x), "f"(v.y), "f"(v.z), "f"(v.w)
                 : "memory");
}

// Deterministic block reduction helper (valid result on thread 0)
__device__ __forceinline__ float block_reduce(float v) {
    __shared__ float sh[32];
    int lane = threadIdx.x & 31;
    int wid  = threadIdx.x >> 5;
    #pragma unroll
    for (int o = 16; o; o >>= 1) v += __shfl_down_sync(0xffffffffu, v, o);
    if (lane == 0) sh[wid] = v;
    __syncthreads();
    int nw = blockDim.x >> 5;
    v = (threadIdx.x < nw) ? sh[threadIdx.x] : 0.f;
    if (wid == 0) {
        #pragma unroll
        for (int o = 16; o; o >>= 1) v += __shfl_down_sync(0xffffffffu, v, o);
    }
    return v;
}

// ---------------------------------------------------------------------------
// Kernel 1: transpose heads (B,N)->(N,8), zero the net accumulator.
// One thread per (node, batch-half); 512-thread blocks. NO extra work here:
// every prep block is on the edge kernel's critical path (R9 lesson).
// ---------------------------------------------------------------------------
__global__ void __launch_bounds__(512)
prep_kernel(const float* __restrict__ heads) {
    int t = blockIdx.x * blockDim.x + threadIdx.x;
    int n = t >> 1;
    int h = t & 1;          // which half: batches 0-3 or 4-7
    if (n >= Nc) return;
    const float* hp = heads + (h * 4) * Nc + n;
    float4 a;
    a.x = hp[0 * Nc];
    a.y = hp[1 * Nc];
    a.z = hp[2 * Nc];
    a.w = hp[3 * Nc];
    reinterpret_cast<float4*>(g_heads_t)[2 * n + h] = a;
    reinterpret_cast<float4*>(g_net)[2 * n + h] = make_float4(0.f, 0.f, 0.f, 0.f);
}

// ---------------------------------------------------------------------------
// Kernel 2: lane-pair decomposition — 2 threads per edge (even lane: batches
// 0-3, odd lane: batches 4-7). Adjacent lanes touch the SAME 128-B L1 line
// per gathered endpoint -> gather L1 wavefronts halve vs one-thread-per-edge.
// ei/ea loads are pair-broadcast (merged); LTS sector traffic unchanged.
// Measured: 84.5us, LTS ~81%+ — at the chip's L2 throughput floor.
// edge_index is INT32 (JAX x64-disabled: "int64" randint is silently int32).
// ---------------------------------------------------------------------------
__global__ void __launch_bounds__(256)
edge_kernel(const int* __restrict__ ei,
            const float2* __restrict__ ea,
            float* __restrict__ flows) {
    int t = blockIdx.x * blockDim.x + threadIdx.x;   // grid exact: 2*Ec % 256 == 0
    int e = t >> 1;
    int h = t & 1;          // batch half

    int s = ei[e];
    int d = ei[Ec + e];
    float cond = ea[e].x;

    const float4* ht = reinterpret_cast<const float4*>(g_heads_t);
    float4 hs = ht[2 * s + h];
    float4 hd = ht[2 * d + h];

    float4 f;
    f.x = cond * (hs.x - hd.x);
    f.y = cond * (hs.y - hd.y);
    f.z = cond * (hs.z - hd.z);
    f.w = cond * (hs.w - hd.w);

    // flows output (B, E): per batch row, same-parity lanes write consecutive e.
    // NOTE: flows = d_out + 3 is only 4B-aligned — scalar stores are mandatory.
    long long b0 = (long long)(4 * h) * Ec + e;
    flows[b0]           = f.x;
    flows[b0 + 1LL*Ec]  = f.y;
    flows[b0 + 2LL*Ec]  = f.z;
    flows[b0 + 3LL*Ec]  = f.w;

    if (s != d) {  // self-edge contributes exactly zero net flow
        red_add_v4(&g_net[s * 8 + 4 * h], f);
        float4 nf = make_float4(-f.x, -f.y, -f.z, -f.w);
        red_add_v4(&g_net[d * 8 + 4 * h], nf);
    }
}

// ---------------------------------------------------------------------------
// Kernel 3: continuity partial sums (blocks 0..195, 2 nodes/thread) PLUS
// boundary loss in extra block 196 (overlapped with the continuity blocks —
// loss_kernel's successor is tiny, so its tail is nearly free).
// reservoir_nodes is INT32 (same JAX x64 trap).
// ---------------------------------------------------------------------------
__global__ void __launch_bounds__(256)
loss_kernel(const float* __restrict__ demands,
            const float* __restrict__ heads,
            const int*   __restrict__ res,
            const float* __restrict__ rhead) {
    if (blockIdx.x == LOSS_BLOCKS) {   // boundary block: 512 items, 2/thread
        float rh = rhead[0];
        float acc = 0.f;
        #pragma unroll
        for (int k = 0; k < 2; k++) {
            int i = threadIdx.x + k * 256;
            int b = i >> 6;            // 8 batches
            int j = i & 63;            // 64 reservoir nodes
            int r = res[j];
            float v = heads[(long long)b * Nc + r] - rh;
            acc += v * v;
        }
        float bsum = block_reduce(acc);
        if (threadIdx.x == 0) g_boundary = bsum;
        return;
    }

    float acc = 0.f;
    const float4* nf = reinterpret_cast<const float4*>(g_net);
    for (int n = blockIdx.x * blockDim.x + threadIdx.x; n < Nc;
         n += LOSS_BLOCKS * blockDim.x) {
        float4 a = nf[2 * n];
        float4 b = nf[2 * n + 1];
        float v;
        v = a.x - demands[0 * Nc + n]; acc += v * v;
        v = a.y - demands[1 * Nc + n]; acc += v * v;
        v = a.z - demands[2 * Nc + n]; acc += v * v;
        v = a.w - demands[3 * Nc + n]; acc += v * v;
        v = b.x - demands[4 * Nc + n]; acc += v * v;
        v = b.y - demands[5 * Nc + n]; acc += v * v;
        v = b.z - demands[6 * Nc + n]; acc += v * v;
        v = b.w - demands[7 * Nc + n]; acc += v * v;
    }
    float s = block_reduce(acc);
    if (threadIdx.x == 0) g_partials[blockIdx.x] = s;
}

// ---------------------------------------------------------------------------
// Kernel 4: final — sum the 196 partials + precomputed boundary sum,
// write the 3 scalars. No scattered gathers on this serial tail.
// ---------------------------------------------------------------------------
__global__ void __launch_bounds__(256)
final_kernel(float* __restrict__ out) {
    int tid = threadIdx.x;
    float acc = (tid < LOSS_BLOCKS) ? g_partials[tid] : 0.f;
    float csum = block_reduce(acc);
    if (tid == 0) {
        float c  = csum / (float)(Bc * Nc);
        float bl = g_boundary / (float)(Bc * 64);
        out[0] = c;
        out[1] = bl;
        out[2] = c + bl;  // LAMBDA_PHYSICS = 1.0
    }
}

// ---------------------------------------------------------------------------
// Launch: prep -> edge -> loss(+boundary block) -> final. Graph-capturable.
// ---------------------------------------------------------------------------
extern "C" void kernel_launch(void* const* d_in, const int* in_sizes, int n_in,
                              void* d_out, int out_size) {
    const float*  node_heads = (const float*)d_in[0];
    const float*  demands    = (const float*)d_in[1];
    const int*    edge_index = (const int*)d_in[2];     // int32!
    const float2* edge_attr  = (const float2*)d_in[3];
    const int*    res_nodes  = (const int*)d_in[4];     // int32!
    const float*  res_head   = (const float*)d_in[5];

    float* out   = (float*)d_out;
    float* flows = out + 3;  // output layout: [c, b, total, flows(8*E)]

    prep_kernel<<<(2 * Nc + 511) / 512, 512>>>(node_heads);
    edge_kernel<<<(2 * Ec) / 256, 256>>>(edge_index, edge_attr, flows);
    loss_kernel<<<LOSS_BLOCKS + 1, 256>>>(demands, node_heads, res_nodes, res_head);
    final_kernel<<<1, 256>>>(out);
}